// round 4
// baseline (speedup 1.0000x reference)
#include <cuda_runtime.h>
#include <math.h>

#define NH   64
#define NINP 128
#define NHID 512
#define NOUT 256
#define NSM  4
#define TINYF 1e-14f

// ---------------- scratch (device globals; no allocations allowed) ----------
__device__ float g_h1[NH * NHID];             // softplus(GN(w1 @ sub))
__device__ float g_partial[NSM * NH * NOUT];  // softmax per (s,h) laid out [s][h][o]
__device__ float g_out_sm[NOUT * NH];         // sum over s, transposed to [o][h]
__device__ float g_scalar[NOUT * NH];         // ws row sums, [o][h]
__device__ float g_onoff[NH];                 // sigmoid gate per head

// ---------------- reduction helpers -----------------------------------------
__device__ __forceinline__ float warpSum(float v) {
#pragma unroll
    for (int o = 16; o; o >>= 1) v += __shfl_xor_sync(0xffffffffu, v, o);
    return v;
}
__device__ __forceinline__ float warpMax(float v) {
#pragma unroll
    for (int o = 16; o; o >>= 1) v = fmaxf(v, __shfl_xor_sync(0xffffffffu, v, o));
    return v;
}
template <int NW>
__device__ __forceinline__ float blockSum(float v, float* red) {
    int w = threadIdx.x >> 5, lane = threadIdx.x & 31;
    v = warpSum(v);
    __syncthreads();               // protect red from any previous use
    if (lane == 0) red[w] = v;
    __syncthreads();
    float r = (lane < NW) ? red[lane] : 0.f;
    return warpSum(r);             // every thread gets full sum
}
template <int NW>
__device__ __forceinline__ float blockMax(float v, float* red) {
    int w = threadIdx.x >> 5, lane = threadIdx.x & 31;
    v = warpMax(v);
    __syncthreads();
    if (lane == 0) red[w] = v;
    __syncthreads();
    float r = (lane < NW) ? red[lane] : -3.4e38f;
    return warpMax(r);
}

// ---------------- kernel A: sub -> h1 (GN + softplus), one block per head ---
__global__ __launch_bounds__(512) void kA(
    const float* __restrict__ x, const float* __restrict__ qw,
    const float* __restrict__ w1, const float* __restrict__ g1,
    const float* __restrict__ b1)
{
    int h = blockIdx.x;
    __shared__ __align__(16) float qws[NINP];
    __shared__ __align__(16) float sub[NINP];
    __shared__ __align__(16) float h1s[NHID];
    __shared__ float red[16];
    int tid = threadIdx.x, w = tid >> 5, lane = tid & 31;

    if (tid < NINP) qws[tid] = qw[h * NINP + tid];
    __syncthreads();

    // phase 1: sub[r] = dot(x[r,:], qw[h,:]); warp-per-row, 8 rows per warp
    float4 qv = ((const float4*)qws)[lane];
#pragma unroll
    for (int rr = 0; rr < 8; ++rr) {
        int r = w * 8 + rr;
        float4 xv = ((const float4*)(x + (size_t)r * NINP))[lane];
        float p = xv.x * qv.x + xv.y * qv.y + xv.z * qv.z + xv.w * qv.w;
        p = warpSum(p);
        if (lane == 0) sub[r] = p;
    }
    __syncthreads();

    // phase 2: h1pre[o] = dot(w1[h,o,:], sub); warp-per-row, 32 rows per warp
    float4 sv = ((const float4*)sub)[lane];
    const float* w1h = w1 + (size_t)h * NHID * NINP;
#pragma unroll 1
    for (int rr = 0; rr < 32; rr += 2) {
        int r0 = w * 32 + rr;
        float4 a0 = ((const float4*)(w1h + (size_t)r0 * NINP))[lane];
        float4 a1 = ((const float4*)(w1h + (size_t)(r0 + 1) * NINP))[lane];
        float p0 = a0.x * sv.x + a0.y * sv.y + a0.z * sv.z + a0.w * sv.w;
        float p1 = a1.x * sv.x + a1.y * sv.y + a1.z * sv.z + a1.w * sv.w;
        p0 = warpSum(p0);
        p1 = warpSum(p1);
        if (lane == 0) { h1s[r0] = p0; h1s[r0 + 1] = p1; }
    }
    __syncthreads();

    // GroupNorm over NHID (biased var) + softplus
    float v = h1s[tid];
    float s1 = blockSum<16>(v, red);
    float s2 = blockSum<16>(v * v, red);
    float mu = s1 * (1.f / NHID);
    float var = s2 * (1.f / NHID) - mu * mu;
    float zn = (v - mu) * rsqrtf(var + 1e-5f) * g1[h * NHID + tid] + b1[h * NHID + tid];
    float sp = fmaxf(zn, 0.f) + log1pf(expf(-fabsf(zn)));   // stable softplus
    g_h1[h * NHID + tid] = sp;
}

// ---------------- kernel B: z = w2·h1, GN, softmax; one block per (s,h) -----
__global__ __launch_bounds__(256) void kB(
    const float* __restrict__ w2, const float* __restrict__ g2,
    const float* __restrict__ b2)
{
    int sh = blockIdx.x;        // s*64 + h
    int h = sh & 63;
    __shared__ __align__(16) float h1s[NHID];
    __shared__ float zs[NOUT];
    __shared__ float red[8];
    int tid = threadIdx.x, w = tid >> 5, lane = tid & 31;

    h1s[tid]       = g_h1[h * NHID + tid];
    h1s[tid + 256] = g_h1[h * NHID + tid + 256];
    __syncthreads();

    float4 hv[4];
#pragma unroll
    for (int j = 0; j < 4; ++j) hv[j] = ((const float4*)h1s)[j * 32 + lane];

    const float* w2b = w2 + (size_t)sh * NOUT * NHID;
    // warp-per-row, 2 rows in flight (8 float4 loads outstanding per lane)
#pragma unroll 1
    for (int rr = 0; rr < 32; rr += 2) {
        int r0 = w * 32 + rr;
        const float4* p0 = (const float4*)(w2b + (size_t)r0 * NHID);
        const float4* p1 = (const float4*)(w2b + (size_t)(r0 + 1) * NHID);
        float a0 = 0.f, a1 = 0.f;
#pragma unroll
        for (int j = 0; j < 4; ++j) {
            float4 v0 = p0[j * 32 + lane];
            float4 v1 = p1[j * 32 + lane];
            a0 += v0.x * hv[j].x + v0.y * hv[j].y + v0.z * hv[j].z + v0.w * hv[j].w;
            a1 += v1.x * hv[j].x + v1.y * hv[j].y + v1.z * hv[j].z + v1.w * hv[j].w;
        }
        a0 = warpSum(a0);
        a1 = warpSum(a1);
        if (lane == 0) { zs[r0] = a0; zs[r0 + 1] = a1; }
    }
    __syncthreads();

    float z = zs[tid];
    float s1 = blockSum<8>(z, red);
    float s2 = blockSum<8>(z * z, red);
    float mu = s1 * (1.f / NOUT);
    float var = s2 * (1.f / NOUT) - mu * mu;
    float zn = (z - mu) * rsqrtf(var + 1e-5f) * g2[sh * NOUT + tid] + b2[sh * NOUT + tid];

    float m = blockMax<8>(zn, red);
    float e = expf(zn - m);
    float se = blockSum<8>(e, red);
    g_partial[sh * NOUT + tid] = e / se;   // [s][h][o], coalesced
}

// ---------------- kernel C: scalar[o,h] = sum_i ws[h,o,i] -------------------
__global__ __launch_bounds__(256) void kC(const float* __restrict__ ws)
{
    int w = threadIdx.x >> 5, lane = threadIdx.x & 31;
    int wg = blockIdx.x * 8 + w;           // 1024 warps, 16 rows each
#pragma unroll 1
    for (int i = 0; i < 16; ++i) {
        int row = wg * 16 + i;             // row = h*256 + o, 16384 rows
        const float4* p = (const float4*)(ws + (size_t)row * NOUT);
        float a = 0.f;
#pragma unroll
        for (int j = 0; j < 2; ++j) {
            float4 v = p[j * 32 + lane];
            a += v.x + v.y + v.z + v.w;
        }
        a = warpSum(a);
        if (lane == 0) {
            int hh = row >> 8, oo = row & 255;
            g_scalar[oo * NH + hh] = a;
        }
    }
}

// ---------------- kernel D1: last_prod, out_sm reduction over s, gate -------
__global__ __launch_bounds__(256) void kD1(
    const float* __restrict__ last, const float* __restrict__ woo)
{
    __shared__ float lp[NOUT];
    int tid = threadIdx.x;
    int o = tid;

    float prod = 1.f;
#pragma unroll
    for (int hh = 0; hh < NH; ++hh) prod *= last[o * NH + hh];
    lp[o] = prod;

    // out_sm[o][h] = sum_s partial[s][h][o]
    for (int hh = 0; hh < NH; ++hh) {
        float s = 0.f;
#pragma unroll
        for (int s4 = 0; s4 < NSM; ++s4) s += g_partial[(s4 * NH + hh) * NOUT + o];
        g_out_sm[o * NH + hh] = s;
    }
    __syncthreads();

    if (tid < NH) {
        int hh = tid;
        const float* wr = woo + (size_t)hh * 2 * NOUT;
        float gl = 0.f;
        for (int o2 = 0; o2 < NOUT; ++o2) gl += wr[o2] * lp[o2];
        for (int o2 = 0; o2 < NOUT; ++o2) gl += wr[NOUT + o2] * g_out_sm[o2 * NH + hh];
        g_onoff[hh] = 1.f / (1.f + expf(-gl));
    }
}

// ---------------- kernel D2: final elementwise outputs ----------------------
__global__ __launch_bounds__(256) void kD2(float* __restrict__ out)
{
    int idx = blockIdx.x * 256 + threadIdx.x;   // 0..16383, idx = o*64 + h
    int hh = idx & 63;
    float osm = g_out_sm[idx];
    float oo = g_onoff[hh];
    float v = oo * osm;                          // on_off_out_sm (pre-clip)
    out[idx] = fmaxf(v, TINYF);                  // clip(v, TINY, None)
    float v2 = v * g_scalar[idx];                // uses UNclipped v, per reference
    out[NOUT * NH + idx] = (fabsf(v2) <= TINYF) ? TINYF : v2;
}

// ---------------- launch -----------------------------------------------------
extern "C" void kernel_launch(void* const* d_in, const int* in_sizes, int n_in,
                              void* d_out, int out_size)
{
    const float* x    = (const float*)d_in[0];
    const float* last = (const float*)d_in[1];
    const float* qw   = (const float*)d_in[2];
    const float* w1   = (const float*)d_in[3];
    const float* g1   = (const float*)d_in[4];
    const float* b1   = (const float*)d_in[5];
    const float* w2   = (const float*)d_in[6];
    const float* g2   = (const float*)d_in[7];
    const float* b2   = (const float*)d_in[8];
    const float* ws   = (const float*)d_in[9];
    const float* woo  = (const float*)d_in[10];
    float* out = (float*)d_out;

    kA<<<NH, 512>>>(x, qw, w1, g1, b1);
    kC<<<128, 256>>>(ws);
    kB<<<NSM * NH, 256>>>(w2, g2, b2);
    kD1<<<1, 256>>>(last, woo);
    kD2<<<NOUT * NH / 256, 256>>>(out);
}

// round 6
// speedup vs baseline: 2.7756x; 2.7756x over previous
#include <cuda_runtime.h>
#include <math.h>

#define NH   64
#define NINP 128
#define NHID 512
#define NOUT 256
#define NSM  4
#define TINYF 1e-14f

// ---------------- scratch (device globals; no allocations allowed) ----------
__device__ float g_h1pre[NH * NHID];          // w1 @ sub, pre-GN
__device__ float g_h1[NH * NHID];             // softplus(GN(w1 @ sub))
__device__ float g_partial[NSM * NH * NOUT];  // softmax per (s,h) laid out [s][h][o]
__device__ float g_out_sm[NOUT * NH];         // sum over s, [o][h] layout
__device__ float g_out_sm_ho[NH * NOUT];      // same data, [h][o] layout
__device__ float g_scalar[NOUT * NH];         // ws row sums, [o][h]
__device__ float g_lp[NOUT];                  // prod over heads of last_out_sm
__device__ float g_onoff[NH];                 // sigmoid gate per head

// ---------------- reduction helpers -----------------------------------------
__device__ __forceinline__ float warpSum(float v) {
#pragma unroll
    for (int o = 16; o; o >>= 1) v += __shfl_xor_sync(0xffffffffu, v, o);
    return v;
}
__device__ __forceinline__ float warpMax(float v) {
#pragma unroll
    for (int o = 16; o; o >>= 1) v = fmaxf(v, __shfl_xor_sync(0xffffffffu, v, o));
    return v;
}
__device__ __forceinline__ float warpProd(float v) {
#pragma unroll
    for (int o = 16; o; o >>= 1) v *= __shfl_xor_sync(0xffffffffu, v, o);
    return v;
}
template <int NW>
__device__ __forceinline__ float blockSum(float v, float* red) {
    int w = threadIdx.x >> 5, lane = threadIdx.x & 31;
    v = warpSum(v);
    __syncthreads();
    if (lane == 0) red[w] = v;
    __syncthreads();
    float r = (lane < NW) ? red[lane] : 0.f;
    return warpSum(r);
}
template <int NW>
__device__ __forceinline__ float blockMax(float v, float* red) {
    int w = threadIdx.x >> 5, lane = threadIdx.x & 31;
    v = warpMax(v);
    __syncthreads();
    if (lane == 0) red[w] = v;
    __syncthreads();
    float r = (lane < NW) ? red[lane] : -3.4e38f;
    return warpMax(r);
}

// ---------------- kA1: preact = w1 @ (x @ qw_h); block = (h, quarter) -------
__global__ __launch_bounds__(512) void kA1(
    const float* __restrict__ x, const float* __restrict__ qw,
    const float* __restrict__ w1)
{
    int h = blockIdx.x >> 2, c = blockIdx.x & 3;
    __shared__ __align__(16) float qws[NINP];
    __shared__ __align__(16) float sub[NINP];
    int tid = threadIdx.x, w = tid >> 5, lane = tid & 31;

    if (tid < NINP) qws[tid] = qw[h * NINP + tid];
    __syncthreads();

    // sub[r] = dot(x[r,:], qw[h,:]); 16 warps x 8 rows (x is L2-resident)
    float4 qv = ((const float4*)qws)[lane];
#pragma unroll
    for (int rr = 0; rr < 8; ++rr) {
        int r = w * 8 + rr;
        float4 xv = ((const float4*)(x + (size_t)r * NINP))[lane];
        float p = xv.x * qv.x + xv.y * qv.y + xv.z * qv.z + xv.w * qv.w;
        p = warpSum(p);
        if (lane == 0) sub[r] = p;
    }
    __syncthreads();

    // 128 rows of w1 for this (h, c); warp-per-row, 2 rows in flight
    float4 sv = ((const float4*)sub)[lane];
    const float* w1h = w1 + ((size_t)h * NHID + c * 128) * NINP;
    float* dst = g_h1pre + h * NHID + c * 128;
#pragma unroll 1
    for (int rr = 0; rr < 8; rr += 2) {
        int r0 = w * 8 + rr;
        float4 a0 = ((const float4*)(w1h + (size_t)r0 * NINP))[lane];
        float4 a1 = ((const float4*)(w1h + (size_t)(r0 + 1) * NINP))[lane];
        float p0 = a0.x * sv.x + a0.y * sv.y + a0.z * sv.z + a0.w * sv.w;
        float p1 = a1.x * sv.x + a1.y * sv.y + a1.z * sv.z + a1.w * sv.w;
        p0 = warpSum(p0);
        p1 = warpSum(p1);
        if (lane == 0) { dst[r0] = p0; dst[r0 + 1] = p1; }
    }
}

// ---------------- kA2: GroupNorm + softplus over NHID; block per head -------
__global__ __launch_bounds__(512) void kA2(
    const float* __restrict__ g1, const float* __restrict__ b1)
{
    int h = blockIdx.x, tid = threadIdx.x;
    __shared__ float red[16];
    float v = g_h1pre[h * NHID + tid];
    float s1 = blockSum<16>(v, red);
    float s2 = blockSum<16>(v * v, red);
    float mu = s1 * (1.f / NHID);
    float var = s2 * (1.f / NHID) - mu * mu;
    float zn = (v - mu) * rsqrtf(var + 1e-5f) * g1[h * NHID + tid] + b1[h * NHID + tid];
    float sp = fmaxf(zn, 0.f) + log1pf(expf(-fabsf(zn)));
    g_h1[h * NHID + tid] = sp;
}

// ---------------- kBC: fused kB (blocks 0..255) + kC (blocks 256..383) ------
__global__ __launch_bounds__(256) void kBC(
    const float* __restrict__ w2, const float* __restrict__ g2,
    const float* __restrict__ b2, const float* __restrict__ ws)
{
    int tid = threadIdx.x, w = tid >> 5, lane = tid & 31;

    if (blockIdx.x >= NSM * NH) {
        // ----- kC: scalar[o,h] = sum_i ws[h,o,i] -----
        int wg = (blockIdx.x - NSM * NH) * 8 + w;   // 1024 warps, 16 rows each
#pragma unroll 1
        for (int i = 0; i < 16; ++i) {
            int row = wg * 16 + i;                  // row = h*256 + o
            const float4* p = (const float4*)(ws + (size_t)row * NOUT);
            float a = 0.f;
#pragma unroll
            for (int j = 0; j < 2; ++j) {
                float4 v = p[j * 32 + lane];
                a += v.x + v.y + v.z + v.w;
            }
            a = warpSum(a);
            if (lane == 0) {
                int hh = row >> 8, oo = row & 255;
                g_scalar[oo * NH + hh] = a;
            }
        }
        return;
    }

    // ----- kB: z = w2·h1, GN, softmax; block per (s,h) -----
    int sh = blockIdx.x;
    int h = sh & 63;
    __shared__ __align__(16) float h1s[NHID];
    __shared__ float zs[NOUT];
    __shared__ float red[8];

    h1s[tid]       = g_h1[h * NHID + tid];
    h1s[tid + 256] = g_h1[h * NHID + tid + 256];
    __syncthreads();

    float4 hv[4];
#pragma unroll
    for (int j = 0; j < 4; ++j) hv[j] = ((const float4*)h1s)[j * 32 + lane];

    const float* w2b = w2 + (size_t)sh * NOUT * NHID;
#pragma unroll 1
    for (int rr = 0; rr < 32; rr += 2) {
        int r0 = w * 32 + rr;
        const float4* p0 = (const float4*)(w2b + (size_t)r0 * NHID);
        const float4* p1 = (const float4*)(w2b + (size_t)(r0 + 1) * NHID);
        float a0 = 0.f, a1 = 0.f;
#pragma unroll
        for (int j = 0; j < 4; ++j) {
            float4 v0 = p0[j * 32 + lane];
            float4 v1 = p1[j * 32 + lane];
            a0 += v0.x * hv[j].x + v0.y * hv[j].y + v0.z * hv[j].z + v0.w * hv[j].w;
            a1 += v1.x * hv[j].x + v1.y * hv[j].y + v1.z * hv[j].z + v1.w * hv[j].w;
        }
        a0 = warpSum(a0);
        a1 = warpSum(a1);
        if (lane == 0) { zs[r0] = a0; zs[r0 + 1] = a1; }
    }
    __syncthreads();

    float z = zs[tid];
    float s1 = blockSum<8>(z, red);
    float s2 = blockSum<8>(z * z, red);
    float mu = s1 * (1.f / NOUT);
    float var = s2 * (1.f / NOUT) - mu * mu;
    float zn = (z - mu) * rsqrtf(var + 1e-5f) * g2[sh * NOUT + tid] + b2[sh * NOUT + tid];

    float m = blockMax<8>(zn, red);
    float e = expf(zn - m);
    float se = blockSum<8>(e, red);
    g_partial[sh * NOUT + tid] = e / se;   // [s][h][o], coalesced
}

// ---------------- kE1: out_sm reduction over s (both layouts) + last_prod ---
__global__ __launch_bounds__(256) void kE1(const float* __restrict__ last)
{
    int tid = threadIdx.x;
    if (blockIdx.x < NH) {
        int h = blockIdx.x, o = tid;
        float s = 0.f;
#pragma unroll
        for (int s4 = 0; s4 < NSM; ++s4) s += g_partial[(s4 * NH + h) * NOUT + o];
        g_out_sm_ho[h * NOUT + o] = s;     // coalesced
        g_out_sm[o * NH + h] = s;          // transposed (L2 scatter, tiny)
    } else {
        // last_prod: warp per output row; 32 blocks x 8 warps = 256 rows
        int b = blockIdx.x - NH;
        int w = tid >> 5, lane = tid & 31;
        int o = b * 8 + w;
        float p = last[o * NH + lane] * last[o * NH + 32 + lane];
        p = warpProd(p);
        if (lane == 0) g_lp[o] = p;
    }
}

// ---------------- kE2: gate logit + sigmoid; warp per head ------------------
__global__ __launch_bounds__(1024) void kE2(const float* __restrict__ woo)
{
    int tid = threadIdx.x, w = tid >> 5, lane = tid & 31;
    int h = blockIdx.x * 32 + w;
    const float* wr = woo + (size_t)h * 2 * NOUT;
    float gl = 0.f;
#pragma unroll
    for (int j = 0; j < 8; ++j) {
        int o = j * 32 + lane;
        gl += wr[o] * g_lp[o] + wr[NOUT + o] * g_out_sm_ho[h * NOUT + o];
    }
    gl = warpSum(gl);
    if (lane == 0) g_onoff[h] = 1.f / (1.f + expf(-gl));
}

// ---------------- kD2: final elementwise outputs ----------------------------
__global__ __launch_bounds__(256) void kD2(float* __restrict__ out)
{
    int idx = blockIdx.x * 256 + threadIdx.x;   // 0..16383, idx = o*64 + h
    int hh = idx & 63;
    float osm = g_out_sm[idx];
    float oo = g_onoff[hh];
    float v = oo * osm;                          // on_off_out_sm (pre-clip)
    out[idx] = fmaxf(v, TINYF);                  // clip(v, TINY, None)
    float v2 = v * g_scalar[idx];                // uses UNclipped v, per reference
    out[NOUT * NH + idx] = (fabsf(v2) <= TINYF) ? TINYF : v2;
}

// ---------------- launch -----------------------------------------------------
extern "C" void kernel_launch(void* const* d_in, const int* in_sizes, int n_in,
                              void* d_out, int out_size)
{
    const float* x    = (const float*)d_in[0];
    const float* last = (const float*)d_in[1];
    const float* qw   = (const float*)d_in[2];
    const float* w1   = (const float*)d_in[3];
    const float* g1   = (const float*)d_in[4];
    const float* b1   = (const float*)d_in[5];
    const float* w2   = (const float*)d_in[6];
    const float* g2   = (const float*)d_in[7];
    const float* b2   = (const float*)d_in[8];
    const float* ws   = (const float*)d_in[9];
    const float* woo  = (const float*)d_in[10];
    float* out = (float*)d_out;

    kA1<<<NH * 4, 512>>>(x, qw, w1);
    kA2<<<NH, 512>>>(g1, b1);
    kBC<<<NSM * NH + 128, 256>>>(w2, g2, b2, ws);
    kE1<<<NH + 32, 256>>>(last);
    kE2<<<2, 1024>>>(woo);
    kD2<<<NOUT * NH / 256, 256>>>(out);
}